// round 1
// baseline (speedup 1.0000x reference)
#include <cuda_runtime.h>

// EMA scan: out[l, d, e] = a_e * x[l, d] + (1 - a_e) * out[l-1, d, e]
// with out[-1, d, e] := x[0, d]  (matches reference: carry init = x[0], scan over all L)
//
// Strategy: chunked scan with warm-up replay.
//   L = 8192 split into 32 chunks of S=256. Each block replays W=512 steps
//   before its chunk (reads only) to reconstruct the carry; truncation error
//   is (1-a_max)^W = 0.9586^512 ~ 4e-10 absolute -> negligible vs 1e-3 tol.
//
// Mapping: block = (chunk, d-group of 128 d's). 512 threads: 4 threads per d,
//   each thread owns 2 EMA states (e0, e0+1) in registers.
//   Stores: per-thread float2 -> warp writes 256B contiguous.

#define LSEQ 8192
#define DFEAT 512
#define EMAS 8
#define CHUNK 256     // output steps per block
#define WARM 512      // warm-up replay steps
#define DGRP 128      // d's per block
#define TPD 4         // threads per d
#define NTHREADS (DGRP * TPD)   // 512

__global__ __launch_bounds__(NTHREADS, 1)
void ema_chunk_kernel(const float* __restrict__ x,
                      const float* __restrict__ log_decay,
                      float* __restrict__ out)
{
    const int t  = threadIdx.x;
    const int dl = t >> 2;          // 0..127  (local d)
    const int q  = t & 3;           // 0..3
    const int e0 = q * 2;           // e in {0,2,4,6}

    const int d = blockIdx.y * DGRP + dl;

    // decays (computed once per thread; 2 states)
    const float la0 = log_decay[e0];
    const float la1 = log_decay[e0 + 1];
    const float a0  = 1.0f / (1.0f + expf(-la0));
    const float a1  = 1.0f / (1.0f + expf(-la1));
    const float o0  = 1.0f - a0;
    const float o1  = 1.0f - a1;

    const int l_real = blockIdx.x * CHUNK;             // first output step
    const int l_start = (l_real >= WARM) ? (l_real - WARM) : 0;

    const float* xp = x + d;

    // carry init: x[l_start, d]. For chunk 0 this is exactly out[-1] = x[0].
    float c0 = xp[(size_t)l_start * DFEAT];
    float c1 = c0;

    // ---- warm-up replay: no stores ----
    #pragma unroll 8
    for (int l = l_start; l < l_real; ++l) {
        const float xv = xp[(size_t)l * DFEAT];
        c0 = fmaf(o0, c0, a0 * xv);
        c1 = fmaf(o1, c1, a1 * xv);
    }

    // ---- real chunk: compute + store ----
    float* op = out + (size_t)l_real * (DFEAT * EMAS) + (size_t)d * EMAS + e0;
    #pragma unroll 8
    for (int i = 0; i < CHUNK; ++i) {
        const float xv = xp[(size_t)(l_real + i) * DFEAT];
        c0 = fmaf(o0, c0, a0 * xv);
        c1 = fmaf(o1, c1, a1 * xv);
        float2 v = make_float2(c0, c1);
        *reinterpret_cast<float2*>(op + (size_t)i * (DFEAT * EMAS)) = v;
    }
}

extern "C" void kernel_launch(void* const* d_in, const int* in_sizes, int n_in,
                              void* d_out, int out_size)
{
    // inputs per metadata order: x (L*D), log_decay (EMAS). Be robust to order
    // by checking sizes.
    const float* x  = (const float*)d_in[0];
    const float* ld = (const float*)d_in[1];
    if (n_in >= 2 && in_sizes[0] == EMAS && in_sizes[1] == LSEQ * DFEAT) {
        x  = (const float*)d_in[1];
        ld = (const float*)d_in[0];
    }
    float* out = (float*)d_out;

    dim3 grid(LSEQ / CHUNK, DFEAT / DGRP);   // (32, 4) = 128 blocks
    ema_chunk_kernel<<<grid, NTHREADS>>>(x, ld, out);
}